// round 11
// baseline (speedup 1.0000x reference)
#include <cuda_runtime.h>
#include <cuda_bf16.h>
#include <math.h>
#include <stdint.h>

#define LSEQ   2048
#define BATCH  4
#define NT     8192          // BATCH * LSEQ
#define CDIM   256
#define DIN    512
#define DSTATE 16
#define DTRANK 16
#define NCHUNK 32
#define CHLEN  64            // LSEQ / NCHUNK

// ---------------- scratch (static __device__, no allocs) ----------------
__device__ float g_u    [NT * CDIM];        // (B*L, C)   n-major normalized input
__device__ float g_xz   [2 * DIN * NT];     // (2*DIN, B*L) in_proj output (m-major)
__device__ float g_xc   [DIN * NT];         // (DIN, B*L) conv+silu output
__device__ float g_xpart[4 * 48 * NT];      // x_proj split-K partials
__device__ float g_dt   [NT * DTRANK];      // (B*L, 16)
__device__ float g_Bm   [NT * DSTATE];      // (B*L, 16)
__device__ float g_Cm   [NT * DSTATE];      // (B*L, 16)
__device__ float g_delta[DIN * NT];         // (DIN, B*L) softplus(dt_proj)
__device__ float g_y    [NT * DIN];         // (B*L, DIN) n-major gated scan output
__device__ float g_op   [CDIM * NT];        // (C, B*L) out_proj output
__device__ float g_P    [BATCH * NCHUNK * DIN * DSTATE];
__device__ float g_q    [BATCH * NCHUNK * DIN * DSTATE];
__device__ float g_h0   [BATCH * NCHUNK * DIN * DSTATE];

__device__ __forceinline__ uint32_t s2u(const void* p) {
    return (uint32_t)__cvta_generic_to_shared(p);
}
__device__ __forceinline__ void ldsm4(uint32_t* r, uint32_t addr) {
    asm volatile("ldmatrix.sync.aligned.m8n8.x4.shared.b16 {%0,%1,%2,%3}, [%4];"
        : "=r"(r[0]), "=r"(r[1]), "=r"(r[2]), "=r"(r[3]) : "r"(addr));
}
__device__ __forceinline__ void mma16816(float* c, const uint32_t* a, uint32_t b0, uint32_t b1) {
    asm volatile("mma.sync.aligned.m16n8k16.row.col.f32.bf16.bf16.f32 "
        "{%0,%1,%2,%3}, {%4,%5,%6,%7}, {%8,%9}, {%0,%1,%2,%3};"
        : "+f"(c[0]), "+f"(c[1]), "+f"(c[2]), "+f"(c[3])
        : "r"(a[0]), "r"(a[1]), "r"(a[2]), "r"(a[3]), "r"(b0), "r"(b1));
}

// FMA-pipe exp: exp(x) = 2^(x*log2e); magic-number rounding + deg-5 poly.
// rel err ~2e-8 on clamped range; NO MUFU usage.
__device__ __forceinline__ float fexp(float x) {
    x = fminf(fmaxf(x, -80.f), 80.f);
    float t  = fmaf(x, 1.4426950408889634f, 12582912.0f);   // 1.5*2^23
    int   ni = __float_as_int(t) - 0x4B400000;
    float fn = t - 12582912.0f;
    float f  = fmaf(x, 1.4426950408889634f, -fn);
    f = fmaf(x, 1.9259629911266175e-8f, f);                 // log2e lo-part
    float p = 1.3333558146e-3f;
    p = fmaf(p, f, 9.6179664508e-3f);
    p = fmaf(p, f, 5.5503429174e-2f);
    p = fmaf(p, f, 2.4022650696e-1f);
    p = fmaf(p, f, 6.9314718056e-1f);
    p = fmaf(p, f, 1.0f);
    return __int_as_float(__float_as_int(p) + (ni << 23));
}

// ---------------- K1: input LayerNorm (over C), output n-major (NT, C) ----
__global__ void ln_in_kernel(const float* __restrict__ x,
                             const float* __restrict__ w,
                             const float* __restrict__ bias) {
    int b  = blockIdx.y;
    int tid = threadIdx.x;
    int lx = tid & 31;
    int ty = tid >> 5;
    int l0 = blockIdx.x * 32;
    __shared__ float T[CDIM][33];
    __shared__ float sS[8][32], sQ[8][32], sMean[32], sR[32];

    const float* xb = x + (size_t)b * CDIM * LSEQ + l0 + lx;
    float s = 0.f, q = 0.f;
    for (int c = ty; c < CDIM; c += 8) {
        float v = xb[(size_t)c * LSEQ];
        T[c][lx] = v;
        s += v; q += v * v;
    }
    sS[ty][lx] = s; sQ[ty][lx] = q;
    __syncthreads();
    if (ty == 0) {
        float ts = 0.f, tq = 0.f;
        #pragma unroll
        for (int i = 0; i < 8; i++) { ts += sS[i][lx]; tq += sQ[i][lx]; }
        float m   = ts * (1.f / CDIM);
        float var = tq * (1.f / CDIM) - m * m;
        sMean[lx] = m;
        sR[lx]    = rsqrtf(var + 1e-5f);
    }
    __syncthreads();
    int c = tid;
    float wc = w[c], bc = bias[c];
    #pragma unroll 4
    for (int l = 0; l < 32; l++) {
        float v = T[c][l];
        g_u[(size_t)(b * LSEQ + l0 + l) * CDIM + c] = (v - sMean[l]) * sR[l] * wc + bc;
    }
}

// ---------------- K2: tensor-core TN GEMM, bf16 hi/lo, reg-prefetch ---------
// C[M,N] = A[M,K] * Bn[N,K]^T.  BM=128 BN=64 BK=32; 8 warps 4(m)x2(n).
__global__ __launch_bounds__(256, 2)
void gemm_tc_kernel(const float* __restrict__ A, const float* __restrict__ Bn,
                    float* __restrict__ C, int M, int N, int K) {
    __shared__ __nv_bfloat16 Ah[128][40], Al[128][40], Bh[64][40], Bl[64][40];
    const int tid = threadIdx.x, lane = tid & 31, wid = tid >> 5;
    const int m0 = blockIdx.y * 128, n0 = blockIdx.x * 64;
    const int wm = (wid & 3) * 32;
    const int wn = (wid >> 2) * 32;
    const int lr = lane & 15;
    const int lc = (lane & 16) ? 8 : 0;

    float acc[2][4][4];
    #pragma unroll
    for (int mi = 0; mi < 2; mi++)
        #pragma unroll
        for (int nf = 0; nf < 4; nf++)
            #pragma unroll
            for (int e = 0; e < 4; e++) acc[mi][nf][e] = 0.f;

    const int grow = tid >> 3;           // 0..31
    const int gcol = (tid & 7) << 2;     // 0..28

    const float* Abase = A + (size_t)(m0 + grow) * K + gcol;
    const float* Bbase = Bn + (size_t)(n0 + grow) * K + gcol;

    float4 va[4], vb[2];
    #pragma unroll
    for (int i = 0; i < 4; i++) va[i] = *(const float4*)(Abase + (size_t)(32 * i) * K);
    #pragma unroll
    for (int i = 0; i < 2; i++) vb[i] = *(const float4*)(Bbase + (size_t)(32 * i) * K);

    const int nk = K >> 5;
    for (int kt = 0; kt < nk; kt++) {
        // ---- store+convert current regs to smem ----
        #pragma unroll
        for (int i = 0; i < 4; i++) {
            int r = grow + 32 * i;
            float4 v = va[i];
            __nv_bfloat16 h0 = __float2bfloat16(v.x);
            __nv_bfloat16 h1 = __float2bfloat16(v.y);
            __nv_bfloat16 h2 = __float2bfloat16(v.z);
            __nv_bfloat16 h3 = __float2bfloat16(v.w);
            __nv_bfloat162 hh0; hh0.x = h0; hh0.y = h1;
            __nv_bfloat162 hh1; hh1.x = h2; hh1.y = h3;
            *(__nv_bfloat162*)&Ah[r][gcol]     = hh0;
            *(__nv_bfloat162*)&Ah[r][gcol + 2] = hh1;
            __nv_bfloat162 ll0, ll1;
            ll0.x = __float2bfloat16(v.x - __bfloat162float(h0));
            ll0.y = __float2bfloat16(v.y - __bfloat162float(h1));
            ll1.x = __float2bfloat16(v.z - __bfloat162float(h2));
            ll1.y = __float2bfloat16(v.w - __bfloat162float(h3));
            *(__nv_bfloat162*)&Al[r][gcol]     = ll0;
            *(__nv_bfloat162*)&Al[r][gcol + 2] = ll1;
        }
        #pragma unroll
        for (int i = 0; i < 2; i++) {
            int r = grow + 32 * i;
            float4 v = vb[i];
            __nv_bfloat16 h0 = __float2bfloat16(v.x);
            __nv_bfloat16 h1 = __float2bfloat16(v.y);
            __nv_bfloat16 h2 = __float2bfloat16(v.z);
            __nv_bfloat16 h3 = __float2bfloat16(v.w);
            __nv_bfloat162 hh0; hh0.x = h0; hh0.y = h1;
            __nv_bfloat162 hh1; hh1.x = h2; hh1.y = h3;
            *(__nv_bfloat162*)&Bh[r][gcol]     = hh0;
            *(__nv_bfloat162*)&Bh[r][gcol + 2] = hh1;
            __nv_bfloat162 ll0, ll1;
            ll0.x = __float2bfloat16(v.x - __bfloat162float(h0));
            ll0.y = __float2bfloat16(v.y - __bfloat162float(h1));
            ll1.x = __float2bfloat16(v.z - __bfloat162float(h2));
            ll1.y = __float2bfloat16(v.w - __bfloat162float(h3));
            *(__nv_bfloat162*)&Bl[r][gcol]     = ll0;
            *(__nv_bfloat162*)&Bl[r][gcol + 2] = ll1;
        }
        __syncthreads();

        // ---- prefetch next k-tile into regs (overlaps MMA section) ----
        if (kt + 1 < nk) {
            const float* Ap = Abase + (kt + 1) * 32;
            const float* Bp = Bbase + (kt + 1) * 32;
            #pragma unroll
            for (int i = 0; i < 4; i++) va[i] = *(const float4*)(Ap + (size_t)(32 * i) * K);
            #pragma unroll
            for (int i = 0; i < 2; i++) vb[i] = *(const float4*)(Bp + (size_t)(32 * i) * K);
        }

        #pragma unroll
        for (int kk = 0; kk < 2; kk++) {
            const int k16 = kk * 16;
            uint32_t ah[2][4], al[2][4], bh[2][4], bl[2][4];
            #pragma unroll
            for (int mi = 0; mi < 2; mi++) {
                ldsm4(ah[mi], s2u(&Ah[wm + mi * 16 + lr][k16 + lc]));
                ldsm4(al[mi], s2u(&Al[wm + mi * 16 + lr][k16 + lc]));
            }
            #pragma unroll
            for (int nj = 0; nj < 2; nj++) {
                ldsm4(bh[nj], s2u(&Bh[wn + nj * 16 + lr][k16 + lc]));
                ldsm4(bl[nj], s2u(&Bl[wn + nj * 16 + lr][k16 + lc]));
            }
            #pragma unroll
            for (int mi = 0; mi < 2; mi++)
                #pragma unroll
                for (int nf = 0; nf < 4; nf++) {
                    int nj = nf >> 1, sub = nf & 1;
                    mma16816(acc[mi][nf], ah[mi], bh[nj][sub], bh[nj][sub + 2]);
                    mma16816(acc[mi][nf], ah[mi], bl[nj][sub], bl[nj][sub + 2]);
                    mma16816(acc[mi][nf], al[mi], bh[nj][sub], bh[nj][sub + 2]);
                }
        }
        __syncthreads();
    }

    #pragma unroll
    for (int mi = 0; mi < 2; mi++)
        #pragma unroll
        for (int nf = 0; nf < 4; nf++) {
            int row = m0 + wm + mi * 16 + (lane >> 2);
            int col = n0 + wn + nf * 8 + ((lane & 3) << 1);
            float2 v0; v0.x = acc[mi][nf][0]; v0.y = acc[mi][nf][1];
            float2 v1; v1.x = acc[mi][nf][2]; v1.y = acc[mi][nf][3];
            *(float2*)&C[(size_t)row * N + col]       = v0;
            *(float2*)&C[(size_t)(row + 8) * N + col] = v1;
        }
}

// ---------------- K3: causal depthwise conv (width 4) + SiLU ----------------
__global__ void conv_kernel(const float* __restrict__ cw,
                            const float* __restrict__ cb) {
    int d = blockIdx.y;
    int n = blockIdx.x * 256 + threadIdx.x;
    const float* xin = g_xz + (size_t)d * NT;
    float w0 = cw[d * 4 + 0], w1 = cw[d * 4 + 1];
    float w2 = cw[d * 4 + 2], w3 = cw[d * 4 + 3];
    int l = n & (LSEQ - 1);
    float v = cb[d] + w3 * xin[n];
    if (l >= 1) v = fmaf(w2, xin[n - 1], v);
    if (l >= 2) v = fmaf(w1, xin[n - 2], v);
    if (l >= 3) v = fmaf(w0, xin[n - 3], v);
    v = v / (1.f + __expf(-v));          // SiLU
    g_xc[(size_t)d * NT + n] = v;
}

// ---------------- K4a: x_proj split-K partials ------------------------------
__global__ void xproj_part_kernel(const float* __restrict__ W) {
    __shared__ float Ws[48][64];
    __shared__ float Xs[64][68];
    int t  = threadIdx.x;
    int n0 = blockIdx.x * 64;
    int ks = blockIdx.y;
    int tn = t & 63, tk = t >> 6;
    float acc[12];
    #pragma unroll
    for (int j = 0; j < 12; j++) acc[j] = 0.f;

    for (int cc = 0; cc < 2; cc++) {
        int d0 = ks * 128 + cc * 64;
        __syncthreads();
        for (int i = t; i < 768; i += 256) {
            int r = i >> 4, c4 = (i & 15) << 2;
            *(float4*)&Ws[r][c4] = *(const float4*)&W[(size_t)r * DIN + d0 + c4];
        }
        for (int i = t; i < 1024; i += 256) {
            int r = i >> 4, c4 = (i & 15) << 2;
            *(float4*)&Xs[r][c4] = *(const float4*)&g_xc[(size_t)(d0 + r) * NT + n0 + c4];
        }
        __syncthreads();
        #pragma unroll 4
        for (int dd = 0; dd < 64; dd++) {
            float xv = Xs[dd][tn];
            #pragma unroll
            for (int j = 0; j < 12; j++)
                acc[j] = fmaf(xv, Ws[tk * 12 + j][dd], acc[j]);
        }
    }
    int n = n0 + tn;
    #pragma unroll
    for (int j = 0; j < 12; j++) {
        int k = tk * 12 + j;
        g_xpart[((size_t)ks * 48 + k) * NT + n] = acc[j];
    }
}

// ---------------- K4b: reduce partials -> dt/Bm/Cm in (n,16) layout ---------
__global__ void xred_kernel() {
    int idx = blockIdx.x * 256 + threadIdx.x;       // 48 * NT
    int k = idx / NT, n = idx - k * NT;
    float s = g_xpart[(size_t)k * NT + n]
            + g_xpart[((size_t)48 + k) * NT + n]
            + g_xpart[((size_t)96 + k) * NT + n]
            + g_xpart[((size_t)144 + k) * NT + n];
    if (k < DTRANK)                g_dt[(size_t)n * 16 + k] = s;
    else if (k < DTRANK + DSTATE)  g_Bm[(size_t)n * 16 + (k - DTRANK)] = s;
    else                           g_Cm[(size_t)n * 16 + (k - DTRANK - DSTATE)] = s;
}

// ---------------- K5: delta = softplus(dt @ dtw^T + dtb), smem-tiled --------
__global__ void delta_kernel(const float* __restrict__ dtw,
                             const float* __restrict__ dtb) {
    __shared__ float sDt[256][17];
    __shared__ float sW[128][17];
    __shared__ float sB[128];
    int t = threadIdx.x;
    int n0 = blockIdx.x * 256;
    int dseg = blockIdx.y * 128;

    for (int i = t; i < 256 * 4; i += 256) {
        int r = i >> 2, c4 = (i & 3) << 2;
        float4 v = *(const float4*)&g_dt[(size_t)(n0 + r) * 16 + c4];
        sDt[r][c4 + 0] = v.x; sDt[r][c4 + 1] = v.y;
        sDt[r][c4 + 2] = v.z; sDt[r][c4 + 3] = v.w;
    }
    for (int i = t; i < 128 * 4; i += 256) {
        int r = i >> 2, c4 = (i & 3) << 2;
        float4 v = *(const float4*)&dtw[(size_t)(dseg + r) * 16 + c4];
        sW[r][c4 + 0] = v.x; sW[r][c4 + 1] = v.y;
        sW[r][c4 + 2] = v.z; sW[r][c4 + 3] = v.w;
    }
    if (t < 128) sB[t] = dtb[dseg + t];
    __syncthreads();

    int n = n0 + t;
    for (int dd = 0; dd < 128; dd++) {
        float s = sB[dd];
        #pragma unroll
        for (int k = 0; k < 16; k++)
            s = fmaf(sDt[t][k], sW[dd][k], s);
        float delta = (s > 20.f) ? s : log1pf(__expf(s));
        g_delta[(size_t)(dseg + dd) * NT + n] = delta;
    }
}

// ---------------- K6a: chunk scan pass1 — smem-shared B chunk ---------------
__global__ void scan_p1_kernel(const float* __restrict__ Alog) {
    __shared__ float sB[CHLEN][16];
    int b  = blockIdx.z;
    int ch = blockIdx.y;
    int g  = threadIdx.x >> 4;
    int nl = threadIdx.x & 15;
    int d0 = blockIdx.x * 128;
    int base = b * LSEQ + ch * CHLEN;

    {
        int t = threadIdx.x;
        float4 v = *(const float4*)&g_Bm[((size_t)base) * 16 + t * 4];
        *(float4*)&sB[(t * 4) >> 4][(t * 4) & 15] = v;
    }
    __syncthreads();

    for (int dt = 0; dt < 8; dt++) {
        int d = d0 + dt * 16 + g;
        float Adn = -__expf(Alog[d * DSTATE + nl]);
        float P = 1.f, q = 0.f;
        const float* drow  = g_delta + (size_t)d * NT + base;
        const float* xcrow = g_xc    + (size_t)d * NT + base;
        #pragma unroll 4
        for (int l = 0; l < CHLEN; l++) {
            float delta = drow[l];
            float dA = fexp(delta * Adn);
            q = fmaf(dA, q, delta * sB[l][nl] * xcrow[l]);
            P *= dA;
        }
        size_t idx = ((size_t)(b * NCHUNK + ch) * DIN + d) * 16 + nl;
        g_P[idx] = P;
        g_q[idx] = q;
    }
}

// ---------------- K6b: prefix over chunks -> h0 -----------------------------
__global__ void scan_p2_kernel() {
    int idx = blockIdx.x * 256 + threadIdx.x;
    int n = idx & 15;
    int d = (idx >> 4) & (DIN - 1);
    int b = idx >> 13;
    float h = 0.f;
    #pragma unroll
    for (int ch = 0; ch < NCHUNK; ch++) {
        size_t p = ((size_t)(b * NCHUNK + ch) * DIN + d) * 16 + n;
        g_h0[p] = h;
        h = fmaf(g_P[p], h, g_q[p]);
    }
}

// ---------------- K6c: replay + y + gating — smem-shared B/C chunks ---------
__global__ void scan_p3_kernel(const float* __restrict__ Alog,
                               const float* __restrict__ Dp) {
    __shared__ float sB[CHLEN][16];
    __shared__ float sC[CHLEN][16];
    int b  = blockIdx.z;
    int ch = blockIdx.y;
    int g  = threadIdx.x >> 4;
    int nl = threadIdx.x & 15;
    int d0 = blockIdx.x * 128;
    int base = b * LSEQ + ch * CHLEN;

    {
        int t = threadIdx.x;
        float4 v = *(const float4*)&g_Bm[((size_t)base) * 16 + t * 4];
        *(float4*)&sB[(t * 4) >> 4][(t * 4) & 15] = v;
        float4 w = *(const float4*)&g_Cm[((size_t)base) * 16 + t * 4];
        *(float4*)&sC[(t * 4) >> 4][(t * 4) & 15] = w;
    }
    __syncthreads();

    for (int dt = 0; dt < 8; dt++) {
        int d = d0 + dt * 16 + g;
        float Adn = -__expf(Alog[d * DSTATE + nl]);
        float Dd  = Dp[d];
        float h = g_h0[((size_t)(b * NCHUNK + ch) * DIN + d) * 16 + nl];
        const float* drow  = g_delta + (size_t)d * NT + base;
        const float* xcrow = g_xc    + (size_t)d * NT + base;
        const float* zrow  = g_xz + (size_t)(DIN + d) * NT + base;
        #pragma unroll 4
        for (int l = 0; l < CHLEN; l++) {
            float delta = drow[l];
            float xcv = xcrow[l];
            float dA = fexp(delta * Adn);
            h = fmaf(dA, h, delta * sB[l][nl] * xcv);
            float yv = h * sC[l][nl];
            yv += __shfl_xor_sync(0xffffffffu, yv, 1);
            yv += __shfl_xor_sync(0xffffffffu, yv, 2);
            yv += __shfl_xor_sync(0xffffffffu, yv, 4);
            yv += __shfl_xor_sync(0xffffffffu, yv, 8);
            if (nl == 0) {
                float zl = zrow[l];
                float silu = zl / (1.f + __expf(-zl));
                g_y[(size_t)(base + l) * DIN + d] = (yv + Dd * xcv) * silu;
            }
        }
    }
}

// ---------------- K7: residual + output LayerNorm, write (B,C,L,1) ----------
__global__ void ln_out_kernel(const float* __restrict__ x,
                              const float* __restrict__ w,
                              const float* __restrict__ bias,
                              float* __restrict__ out) {
    int b  = blockIdx.y;
    int lx = threadIdx.x;
    int ty = threadIdx.y;
    int l  = blockIdx.x * 32 + lx;
    __shared__ float sS[8][32], sQ[8][32], sMean[32], sR[32];

    const float* xb = x + (size_t)b * CDIM * LSEQ + l;
    const float* ob = g_op + (size_t)b * LSEQ + l;
    float s = 0.f, q = 0.f;
    for (int c = ty; c < CDIM; c += 8) {
        float v = ob[(size_t)c * NT] + xb[(size_t)c * LSEQ];
        s += v; q += v * v;
    }
    sS[ty][lx] = s; sQ[ty][lx] = q;
    __syncthreads();
    if (ty == 0) {
        float ts = 0.f, tq = 0.f;
        #pragma unroll
        for (int i = 0; i < 8; i++) { ts += sS[i][lx]; tq += sQ[i][lx]; }
        float m   = ts * (1.f / CDIM);
        float var = tq * (1.f / CDIM) - m * m;
        sMean[lx] = m;
        sR[lx]    = rsqrtf(var + 1e-5f);
    }
    __syncthreads();
    float m = sMean[lx], r = sR[lx];
    float* outb = out + (size_t)b * CDIM * LSEQ + l;
    for (int c = ty; c < CDIM; c += 8) {
        float v = ob[(size_t)c * NT] + xb[(size_t)c * LSEQ];
        outb[(size_t)c * LSEQ] = (v - m) * r * w[c] + bias[c];
    }
}

// ---------------- launch -----------------------------------------------------
extern "C" void kernel_launch(void* const* d_in, const int* in_sizes, int n_in,
                              void* d_out, int out_size) {
    const float* x         = (const float*)d_in[0];
    const float* ln_w      = (const float*)d_in[1];
    const float* ln_b      = (const float*)d_in[2];
    const float* in_proj_w = (const float*)d_in[3];
    const float* conv_w    = (const float*)d_in[4];
    const float* conv_b    = (const float*)d_in[5];
    const float* x_proj_w  = (const float*)d_in[6];
    const float* dt_proj_w = (const float*)d_in[7];
    const float* dt_proj_b = (const float*)d_in[8];
    const float* A_log     = (const float*)d_in[9];
    const float* Dv        = (const float*)d_in[10];
    const float* out_proj_w= (const float*)d_in[11];
    float* out = (float*)d_out;

    float *p_u, *p_xz, *p_y, *p_op;
    cudaGetSymbolAddress((void**)&p_u,  g_u);
    cudaGetSymbolAddress((void**)&p_xz, g_xz);
    cudaGetSymbolAddress((void**)&p_y,  g_y);
    cudaGetSymbolAddress((void**)&p_op, g_op);

    ln_in_kernel<<<dim3(LSEQ / 32, BATCH), 256>>>(x, ln_w, ln_b);

    // in_proj: (1024,256) @ (8192,256)^T
    gemm_tc_kernel<<<dim3(NT / 64, (2 * DIN) / 128), 256>>>(
        in_proj_w, p_u, p_xz, 2 * DIN, NT, CDIM);

    conv_kernel<<<dim3(NT / 256, DIN), 256>>>(conv_w, conv_b);

    xproj_part_kernel<<<dim3(NT / 64, 4), 256>>>(x_proj_w);
    xred_kernel<<<(48 * NT) / 256, 256>>>();

    delta_kernel<<<dim3(NT / 256, 4), 256>>>(dt_proj_w, dt_proj_b);

    scan_p1_kernel<<<dim3(4, NCHUNK, BATCH), 256>>>(A_log);
    scan_p2_kernel<<<dim3(BATCH * DIN * 16 / 256), 256>>>();
    scan_p3_kernel<<<dim3(4, NCHUNK, BATCH), 256>>>(A_log, Dv);

    // out_proj: (256,512) @ (8192,512)^T
    gemm_tc_kernel<<<dim3(NT / 64, CDIM / 128), 256>>>(
        out_proj_w, p_y, p_op, CDIM, NT, DIN);

    ln_out_kernel<<<dim3(LSEQ / 32, BATCH), dim3(32, 8)>>>(x, ln_w, ln_b, out);
}

// round 12
// speedup vs baseline: 1.1640x; 1.1640x over previous
#include <cuda_runtime.h>
#include <cuda_fp16.h>
#include <math.h>
#include <stdint.h>

#define LSEQ   2048
#define BATCH  4
#define NT     8192          // BATCH * LSEQ
#define CDIM   256
#define DIN    512
#define DSTATE 16
#define DTRANK 16
#define NCHUNK 32
#define CHLEN  64            // LSEQ / NCHUNK

// ---------------- scratch (static __device__, no allocs) ----------------
__device__ float g_u    [NT * CDIM];        // (B*L, C)   n-major normalized input
__device__ float g_xz   [2 * DIN * NT];     // (2*DIN, B*L) in_proj output (m-major)
__device__ float g_xc   [DIN * NT];         // (DIN, B*L) conv+silu output
__device__ float g_xpart[4 * 48 * NT];      // x_proj split-K partials
__device__ float g_dt   [NT * DTRANK];      // (B*L, 16)
__device__ float g_Bm   [NT * DSTATE];      // (B*L, 16)
__device__ float g_Cm   [NT * DSTATE];      // (B*L, 16)
__device__ float g_delta[DIN * NT];         // (DIN, B*L) softplus(dt_proj)
__device__ float g_y    [NT * DIN];         // (B*L, DIN) n-major gated scan output
__device__ float g_op   [CDIM * NT];        // (C, B*L) out_proj output
__device__ float g_P    [BATCH * NCHUNK * DIN * DSTATE];
__device__ float g_q    [BATCH * NCHUNK * DIN * DSTATE];
__device__ float g_h0   [BATCH * NCHUNK * DIN * DSTATE];

__device__ __forceinline__ uint32_t s2u(const void* p) {
    return (uint32_t)__cvta_generic_to_shared(p);
}
__device__ __forceinline__ void ldsm4(uint32_t* r, uint32_t addr) {
    asm volatile("ldmatrix.sync.aligned.m8n8.x4.shared.b16 {%0,%1,%2,%3}, [%4];"
        : "=r"(r[0]), "=r"(r[1]), "=r"(r[2]), "=r"(r[3]) : "r"(addr));
}
__device__ __forceinline__ void mma16816h(float* c, const uint32_t* a, uint32_t b0, uint32_t b1) {
    asm volatile("mma.sync.aligned.m16n8k16.row.col.f32.f16.f16.f32 "
        "{%0,%1,%2,%3}, {%4,%5,%6,%7}, {%8,%9}, {%0,%1,%2,%3};"
        : "+f"(c[0]), "+f"(c[1]), "+f"(c[2]), "+f"(c[3])
        : "r"(a[0]), "r"(a[1]), "r"(a[2]), "r"(a[3]), "r"(b0), "r"(b1));
}

// ---------------- K1: input LayerNorm (over C), output n-major (NT, C) ----
__global__ void ln_in_kernel(const float* __restrict__ x,
                             const float* __restrict__ w,
                             const float* __restrict__ bias) {
    int b  = blockIdx.y;
    int tid = threadIdx.x;
    int lx = tid & 31;
    int ty = tid >> 5;
    int l0 = blockIdx.x * 32;
    __shared__ float T[CDIM][33];
    __shared__ float sS[8][32], sQ[8][32], sMean[32], sR[32];

    const float* xb = x + (size_t)b * CDIM * LSEQ + l0 + lx;
    float s = 0.f, q = 0.f;
    for (int c = ty; c < CDIM; c += 8) {
        float v = xb[(size_t)c * LSEQ];
        T[c][lx] = v;
        s += v; q += v * v;
    }
    sS[ty][lx] = s; sQ[ty][lx] = q;
    __syncthreads();
    if (ty == 0) {
        float ts = 0.f, tq = 0.f;
        #pragma unroll
        for (int i = 0; i < 8; i++) { ts += sS[i][lx]; tq += sQ[i][lx]; }
        float m   = ts * (1.f / CDIM);
        float var = tq * (1.f / CDIM) - m * m;
        sMean[lx] = m;
        sR[lx]    = rsqrtf(var + 1e-5f);
    }
    __syncthreads();
    int c = tid;
    float wc = w[c], bc = bias[c];
    #pragma unroll 4
    for (int l = 0; l < 32; l++) {
        float v = T[c][l];
        g_u[(size_t)(b * LSEQ + l0 + l) * CDIM + c] = (v - sMean[l]) * sR[l] * wc + bc;
    }
}

// ---------------- K2: tensor-core TN GEMM, fp16 A-split 2-term --------------
// C[M,N] = A[M,K] * Bn[N,K]^T.  BM=128 BN=64 BK=32; 8 warps 4(m)x2(n).
// A -> fp16 hi+lo (2 terms); B -> fp16 rounded. err ~2^-11 rel.
__global__ __launch_bounds__(256, 2)
void gemm_tc_kernel(const float* __restrict__ A, const float* __restrict__ Bn,
                    float* __restrict__ C, int M, int N, int K) {
    __shared__ __half Ah[128][40], Al[128][40], Bh[64][40];
    const int tid = threadIdx.x, lane = tid & 31, wid = tid >> 5;
    const int m0 = blockIdx.y * 128, n0 = blockIdx.x * 64;
    const int wm = (wid & 3) * 32;
    const int wn = (wid >> 2) * 32;
    const int lr = lane & 15;
    const int lc = (lane & 16) ? 8 : 0;

    float acc[2][4][4];
    #pragma unroll
    for (int mi = 0; mi < 2; mi++)
        #pragma unroll
        for (int nf = 0; nf < 4; nf++)
            #pragma unroll
            for (int e = 0; e < 4; e++) acc[mi][nf][e] = 0.f;

    const int grow = tid >> 3;           // 0..31
    const int gcol = (tid & 7) << 2;     // 0..28

    const float* Abase = A + (size_t)(m0 + grow) * K + gcol;
    const float* Bbase = Bn + (size_t)(n0 + grow) * K + gcol;

    float4 va[4], vb[2];
    #pragma unroll
    for (int i = 0; i < 4; i++) va[i] = *(const float4*)(Abase + (size_t)(32 * i) * K);
    #pragma unroll
    for (int i = 0; i < 2; i++) vb[i] = *(const float4*)(Bbase + (size_t)(32 * i) * K);

    const int nk = K >> 5;
    for (int kt = 0; kt < nk; kt++) {
        // ---- store+convert current regs to smem ----
        #pragma unroll
        for (int i = 0; i < 4; i++) {
            int r = grow + 32 * i;
            float4 v = va[i];
            __half h0 = __float2half(v.x);
            __half h1 = __float2half(v.y);
            __half h2 = __float2half(v.z);
            __half h3 = __float2half(v.w);
            __half2 hh0; hh0.x = h0; hh0.y = h1;
            __half2 hh1; hh1.x = h2; hh1.y = h3;
            *(__half2*)&Ah[r][gcol]     = hh0;
            *(__half2*)&Ah[r][gcol + 2] = hh1;
            __half2 ll0, ll1;
            ll0.x = __float2half(v.x - __half2float(h0));
            ll0.y = __float2half(v.y - __half2float(h1));
            ll1.x = __float2half(v.z - __half2float(h2));
            ll1.y = __float2half(v.w - __half2float(h3));
            *(__half2*)&Al[r][gcol]     = ll0;
            *(__half2*)&Al[r][gcol + 2] = ll1;
        }
        #pragma unroll
        for (int i = 0; i < 2; i++) {
            int r = grow + 32 * i;
            float4 v = vb[i];
            __half2 hh0, hh1;
            hh0.x = __float2half(v.x); hh0.y = __float2half(v.y);
            hh1.x = __float2half(v.z); hh1.y = __float2half(v.w);
            *(__half2*)&Bh[r][gcol]     = hh0;
            *(__half2*)&Bh[r][gcol + 2] = hh1;
        }
        __syncthreads();

        // ---- prefetch next k-tile into regs (overlaps MMA section) ----
        if (kt + 1 < nk) {
            const float* Ap = Abase + (kt + 1) * 32;
            const float* Bp = Bbase + (kt + 1) * 32;
            #pragma unroll
            for (int i = 0; i < 4; i++) va[i] = *(const float4*)(Ap + (size_t)(32 * i) * K);
            #pragma unroll
            for (int i = 0; i < 2; i++) vb[i] = *(const float4*)(Bp + (size_t)(32 * i) * K);
        }

        #pragma unroll
        for (int kk = 0; kk < 2; kk++) {
            const int k16 = kk * 16;
            uint32_t ah[2][4], al[2][4], bh[2][4];
            #pragma unroll
            for (int mi = 0; mi < 2; mi++) {
                ldsm4(ah[mi], s2u(&Ah[wm + mi * 16 + lr][k16 + lc]));
                ldsm4(al[mi], s2u(&Al[wm + mi * 16 + lr][k16 + lc]));
            }
            #pragma unroll
            for (int nj = 0; nj < 2; nj++)
                ldsm4(bh[nj], s2u(&Bh[wn + nj * 16 + lr][k16 + lc]));
            #pragma unroll
            for (int mi = 0; mi < 2; mi++)
                #pragma unroll
                for (int nf = 0; nf < 4; nf++) {
                    int nj = nf >> 1, sub = nf & 1;
                    mma16816h(acc[mi][nf], ah[mi], bh[nj][sub], bh[nj][sub + 2]);
                    mma16816h(acc[mi][nf], al[mi], bh[nj][sub], bh[nj][sub + 2]);
                }
        }
        __syncthreads();
    }

    #pragma unroll
    for (int mi = 0; mi < 2; mi++)
        #pragma unroll
        for (int nf = 0; nf < 4; nf++) {
            int row = m0 + wm + mi * 16 + (lane >> 2);
            int col = n0 + wn + nf * 8 + ((lane & 3) << 1);
            float2 v0; v0.x = acc[mi][nf][0]; v0.y = acc[mi][nf][1];
            float2 v1; v1.x = acc[mi][nf][2]; v1.y = acc[mi][nf][3];
            *(float2*)&C[(size_t)row * N + col]       = v0;
            *(float2*)&C[(size_t)(row + 8) * N + col] = v1;
        }
}

// ---------------- K3: x_proj split-K partials + fused conv+SiLU -------------
// grid (NT/64, 4). Block computes conv+silu for its 128-d x 64-n tile,
// writes g_xc once, and accumulates the 48x64 x_proj partial.
__global__ void xproj_part_kernel(const float* __restrict__ W,
                                  const float* __restrict__ cw,
                                  const float* __restrict__ cb) {
    __shared__ float Ws[48][64];
    __shared__ float Xr[64][68];     // raw xz, col j <-> n0-4+j
    __shared__ float Xs[64][68];     // conv+silu, col c <-> n0+c
    __shared__ float Cw[64][4];
    __shared__ float Cb[64];
    int t  = threadIdx.x;
    int n0 = blockIdx.x * 64;
    int ks = blockIdx.y;
    int tn = t & 63, tk = t >> 6;
    bool seqstart = (n0 & (LSEQ - 1)) == 0;
    float acc[12];
    #pragma unroll
    for (int j = 0; j < 12; j++) acc[j] = 0.f;

    for (int cc = 0; cc < 2; cc++) {
        int d0 = ks * 128 + cc * 64;
        __syncthreads();
        for (int i = t; i < 768; i += 256) {
            int r = i >> 4, c4 = (i & 15) << 2;
            *(float4*)&Ws[r][c4] = *(const float4*)&W[(size_t)r * DIN + d0 + c4];
        }
        if (t < 64) {
            *(float4*)&Cw[t][0] = *(const float4*)&cw[(d0 + t) * 4];
            Cb[t] = cb[d0 + t];
        }
        for (int i = t; i < 1024; i += 256) {      // main cols j=4..67
            int r = i >> 4, c4 = (i & 15) << 2;
            *(float4*)&Xr[r][4 + c4] = *(const float4*)&g_xz[(size_t)(d0 + r) * NT + n0 + c4];
        }
        if (t < 192) {                              // history cols j=1..3
            int r = t / 3, j = t - r * 3;
            Xr[r][1 + j] = seqstart ? 0.f : g_xz[(size_t)(d0 + r) * NT + n0 - 3 + j];
        }
        __syncthreads();
        for (int i = t; i < 4096; i += 256) {
            int r = i >> 6, c = i & 63;
            float v = Cb[r];
            v = fmaf(Cw[r][3], Xr[r][c + 4], v);
            v = fmaf(Cw[r][2], Xr[r][c + 3], v);
            v = fmaf(Cw[r][1], Xr[r][c + 2], v);
            v = fmaf(Cw[r][0], Xr[r][c + 1], v);
            float xc = v / (1.f + __expf(-v));
            Xs[r][c] = xc;
            g_xc[(size_t)(d0 + r) * NT + n0 + c] = xc;
        }
        __syncthreads();
        #pragma unroll 4
        for (int dd = 0; dd < 64; dd++) {
            float xv = Xs[dd][tn];
            #pragma unroll
            for (int j = 0; j < 12; j++)
                acc[j] = fmaf(xv, Ws[tk * 12 + j][dd], acc[j]);
        }
    }
    int n = n0 + tn;
    #pragma unroll
    for (int j = 0; j < 12; j++) {
        int k = tk * 12 + j;
        g_xpart[((size_t)ks * 48 + k) * NT + n] = acc[j];
    }
}

// ---------------- K4: reduce partials -> dt/Bm/Cm in (n,16) layout ----------
__global__ void xred_kernel() {
    int idx = blockIdx.x * 256 + threadIdx.x;       // 48 * NT
    int k = idx / NT, n = idx - k * NT;
    float s = g_xpart[(size_t)k * NT + n]
            + g_xpart[((size_t)48 + k) * NT + n]
            + g_xpart[((size_t)96 + k) * NT + n]
            + g_xpart[((size_t)144 + k) * NT + n];
    if (k < DTRANK)                g_dt[(size_t)n * 16 + k] = s;
    else if (k < DTRANK + DSTATE)  g_Bm[(size_t)n * 16 + (k - DTRANK)] = s;
    else                           g_Cm[(size_t)n * 16 + (k - DTRANK - DSTATE)] = s;
}

// ---------------- K5: delta = softplus(dt @ dtw^T + dtb), smem-tiled --------
__global__ void delta_kernel(const float* __restrict__ dtw,
                             const float* __restrict__ dtb) {
    __shared__ float sDt[256][17];
    __shared__ float sW[128][17];
    __shared__ float sB[128];
    int t = threadIdx.x;
    int n0 = blockIdx.x * 256;
    int dseg = blockIdx.y * 128;

    for (int i = t; i < 256 * 4; i += 256) {
        int r = i >> 2, c4 = (i & 3) << 2;
        float4 v = *(const float4*)&g_dt[(size_t)(n0 + r) * 16 + c4];
        sDt[r][c4 + 0] = v.x; sDt[r][c4 + 1] = v.y;
        sDt[r][c4 + 2] = v.z; sDt[r][c4 + 3] = v.w;
    }
    for (int i = t; i < 128 * 4; i += 256) {
        int r = i >> 2, c4 = (i & 3) << 2;
        float4 v = *(const float4*)&dtw[(size_t)(dseg + r) * 16 + c4];
        sW[r][c4 + 0] = v.x; sW[r][c4 + 1] = v.y;
        sW[r][c4 + 2] = v.z; sW[r][c4 + 3] = v.w;
    }
    if (t < 128) sB[t] = dtb[dseg + t];
    __syncthreads();

    int n = n0 + t;
    for (int dd = 0; dd < 128; dd++) {
        float s = sB[dd];
        #pragma unroll
        for (int k = 0; k < 16; k++)
            s = fmaf(sDt[t][k], sW[dd][k], s);
        float delta = (s > 20.f) ? s : log1pf(__expf(s));
        g_delta[(size_t)(dseg + dd) * NT + n] = delta;
    }
}

// ---------------- K6a: chunk scan pass1 — smem-shared B chunk ---------------
__global__ void scan_p1_kernel(const float* __restrict__ Alog) {
    __shared__ float sB[CHLEN][16];
    int b  = blockIdx.z;
    int ch = blockIdx.y;
    int g  = threadIdx.x >> 4;
    int nl = threadIdx.x & 15;
    int d0 = blockIdx.x * 128;
    int base = b * LSEQ + ch * CHLEN;

    {
        int t = threadIdx.x;
        float4 v = *(const float4*)&g_Bm[((size_t)base) * 16 + t * 4];
        *(float4*)&sB[(t * 4) >> 4][(t * 4) & 15] = v;
    }
    __syncthreads();

    for (int dt = 0; dt < 8; dt++) {
        int d = d0 + dt * 16 + g;
        float Adn = -__expf(Alog[d * DSTATE + nl]);
        float P = 1.f, q = 0.f;
        const float* drow  = g_delta + (size_t)d * NT + base;
        const float* xcrow = g_xc    + (size_t)d * NT + base;
        #pragma unroll 4
        for (int l = 0; l < CHLEN; l++) {
            float delta = drow[l];
            float dA = __expf(delta * Adn);
            q = fmaf(dA, q, delta * sB[l][nl] * xcrow[l]);
            P *= dA;
        }
        size_t idx = ((size_t)(b * NCHUNK + ch) * DIN + d) * 16 + nl;
        g_P[idx] = P;
        g_q[idx] = q;
    }
}

// ---------------- K6b: prefix over chunks -> h0 -----------------------------
__global__ void scan_p2_kernel() {
    int idx = blockIdx.x * 256 + threadIdx.x;
    int n = idx & 15;
    int d = (idx >> 4) & (DIN - 1);
    int b = idx >> 13;
    float h = 0.f;
    #pragma unroll
    for (int ch = 0; ch < NCHUNK; ch++) {
        size_t p = ((size_t)(b * NCHUNK + ch) * DIN + d) * 16 + n;
        g_h0[p] = h;
        h = fmaf(g_P[p], h, g_q[p]);
    }
}

// ---------------- K6c: replay + y + gating — smem-shared B/C chunks ---------
__global__ void scan_p3_kernel(const float* __restrict__ Alog,
                               const float* __restrict__ Dp) {
    __shared__ float sB[CHLEN][16];
    __shared__ float sC[CHLEN][16];
    int b  = blockIdx.z;
    int ch = blockIdx.y;
    int g  = threadIdx.x >> 4;
    int nl = threadIdx.x & 15;
    int d0 = blockIdx.x * 128;
    int base = b * LSEQ + ch * CHLEN;

    {
        int t = threadIdx.x;
        float4 v = *(const float4*)&g_Bm[((size_t)base) * 16 + t * 4];
        *(float4*)&sB[(t * 4) >> 4][(t * 4) & 15] = v;
        float4 w = *(const float4*)&g_Cm[((size_t)base) * 16 + t * 4];
        *(float4*)&sC[(t * 4) >> 4][(t * 4) & 15] = w;
    }
    __syncthreads();

    for (int dt = 0; dt < 8; dt++) {
        int d = d0 + dt * 16 + g;
        float Adn = -__expf(Alog[d * DSTATE + nl]);
        float Dd  = Dp[d];
        float h = g_h0[((size_t)(b * NCHUNK + ch) * DIN + d) * 16 + nl];
        const float* drow  = g_delta + (size_t)d * NT + base;
        const float* xcrow = g_xc    + (size_t)d * NT + base;
        const float* zrow  = g_xz + (size_t)(DIN + d) * NT + base;
        #pragma unroll 4
        for (int l = 0; l < CHLEN; l++) {
            float delta = drow[l];
            float xcv = xcrow[l];
            float dA = __expf(delta * Adn);
            h = fmaf(dA, h, delta * sB[l][nl] * xcv);
            float yv = h * sC[l][nl];
            yv += __shfl_xor_sync(0xffffffffu, yv, 1);
            yv += __shfl_xor_sync(0xffffffffu, yv, 2);
            yv += __shfl_xor_sync(0xffffffffu, yv, 4);
            yv += __shfl_xor_sync(0xffffffffu, yv, 8);
            if (nl == 0) {
                float zl = zrow[l];
                float silu = zl / (1.f + __expf(-zl));
                g_y[(size_t)(base + l) * DIN + d] = (yv + Dd * xcv) * silu;
            }
        }
    }
}

// ---------------- K7: residual + output LayerNorm, write (B,C,L,1) ----------
__global__ void ln_out_kernel(const float* __restrict__ x,
                              const float* __restrict__ w,
                              const float* __restrict__ bias,
                              float* __restrict__ out) {
    int b  = blockIdx.y;
    int lx = threadIdx.x;
    int ty = threadIdx.y;
    int l  = blockIdx.x * 32 + lx;
    __shared__ float sS[8][32], sQ[8][32], sMean[32], sR[32];

    const float* xb = x + (size_t)b * CDIM * LSEQ + l;
    const float* ob = g_op + (size_t)b * LSEQ + l;
    float s = 0.f, q = 0.f;
    for (int c = ty; c < CDIM; c += 8) {
        float v = ob[(size_t)c * NT] + xb[(size_t)c * LSEQ];
        s += v; q += v * v;
    }
    sS[ty][lx] = s; sQ[ty][lx] = q;
    __syncthreads();
    if (ty == 0) {
        float ts = 0.f, tq = 0.f;
        #pragma unroll
        for (int i = 0; i < 8; i++) { ts += sS[i][lx]; tq += sQ[i][lx]; }
        float m   = ts * (1.f / CDIM);
        float var = tq * (1.f / CDIM) - m * m;
        sMean[lx] = m;
        sR[lx]    = rsqrtf(var + 1e-5f);
    }
    __syncthreads();
    float m = sMean[lx], r = sR[lx];
    float* outb = out + (size_t)b * CDIM * LSEQ + l;
    for (int c = ty; c < CDIM; c += 8) {
        float v = ob[(size_t)c * NT] + xb[(size_t)c * LSEQ];
        outb[(size_t)c * LSEQ] = (v - m) * r * w[c] + bias[c];
    }
}

// ---------------- launch -----------------------------------------------------
extern "C" void kernel_launch(void* const* d_in, const int* in_sizes, int n_in,
                              void* d_out, int out_size) {
    const float* x         = (const float*)d_in[0];
    const float* ln_w      = (const float*)d_in[1];
    const float* ln_b      = (const float*)d_in[2];
    const float* in_proj_w = (const float*)d_in[3];
    const float* conv_w    = (const float*)d_in[4];
    const float* conv_b    = (const float*)d_in[5];
    const float* x_proj_w  = (const float*)d_in[6];
    const float* dt_proj_w = (const float*)d_in[7];
    const float* dt_proj_b = (const float*)d_in[8];
    const float* A_log     = (const float*)d_in[9];
    const float* Dv        = (const float*)d_in[10];
    const float* out_proj_w= (const float*)d_in[11];
    float* out = (float*)d_out;

    float *p_u, *p_xz, *p_y, *p_op;
    cudaGetSymbolAddress((void**)&p_u,  g_u);
    cudaGetSymbolAddress((void**)&p_xz, g_xz);
    cudaGetSymbolAddress((void**)&p_y,  g_y);
    cudaGetSymbolAddress((void**)&p_op, g_op);

    ln_in_kernel<<<dim3(LSEQ / 32, BATCH), 256>>>(x, ln_w, ln_b);

    // in_proj: (1024,256) @ (8192,256)^T
    gemm_tc_kernel<<<dim3(NT / 64, (2 * DIN) / 128), 256>>>(
        in_proj_w, p_u, p_xz, 2 * DIN, NT, CDIM);

    xproj_part_kernel<<<dim3(NT / 64, 4), 256>>>(x_proj_w, conv_w, conv_b);
    xred_kernel<<<(48 * NT) / 256, 256>>>();

    delta_kernel<<<dim3(NT / 256, 4), 256>>>(dt_proj_w, dt_proj_b);

    scan_p1_kernel<<<dim3(4, NCHUNK, BATCH), 256>>>(A_log);
    scan_p2_kernel<<<dim3(BATCH * DIN * 16 / 256), 256>>>();
    scan_p3_kernel<<<dim3(4, NCHUNK, BATCH), 256>>>(A_log, Dv);

    // out_proj: (256,512) @ (8192,512)^T
    gemm_tc_kernel<<<dim3(NT / 64, CDIM / 128), 256>>>(
        out_proj_w, p_y, p_op, CDIM, NT, DIN);

    ln_out_kernel<<<dim3(LSEQ / 32, BATCH), dim3(32, 8)>>>(x, ln_w, ln_b, out);
}

// round 13
// speedup vs baseline: 1.2147x; 1.0435x over previous
#include <cuda_runtime.h>
#include <cuda_fp16.h>
#include <math.h>
#include <stdint.h>

#define LSEQ   2048
#define BATCH  4
#define NT     8192          // BATCH * LSEQ
#define CDIM   256
#define DIN    512
#define DSTATE 16
#define DTRANK 16
#define NCHUNK 32
#define CHLEN  64            // LSEQ / NCHUNK

// ---------------- scratch (static __device__, no allocs) ----------------
__device__ float g_u    [NT * CDIM];        // (B*L, C)   n-major normalized input
__device__ float g_xz   [2 * DIN * NT];     // (2*DIN, B*L) in_proj output (m-major)
__device__ float g_xc   [DIN * NT];         // (DIN, B*L) conv+silu output
__device__ float g_xpart[4 * 48 * NT];      // x_proj split-K partials
__device__ float g_dt   [NT * DTRANK];      // (B*L, 16)
__device__ float g_Bm   [NT * DSTATE];      // (B*L, 16)
__device__ float g_Cm   [NT * DSTATE];      // (B*L, 16)
__device__ float g_delta[DIN * NT];         // (DIN, B*L) softplus(dt_proj)
__device__ float g_y    [NT * DIN];         // (B*L, DIN) n-major gated scan output
__device__ float g_op   [CDIM * NT];        // (C, B*L) out_proj output
__device__ float g_P    [BATCH * NCHUNK * DIN * DSTATE];
__device__ float g_q    [BATCH * NCHUNK * DIN * DSTATE];
__device__ float g_h0   [BATCH * NCHUNK * DIN * DSTATE];

__device__ __forceinline__ uint32_t s2u(const void* p) {
    return (uint32_t)__cvta_generic_to_shared(p);
}
__device__ __forceinline__ void ldsm4(uint32_t* r, uint32_t addr) {
    asm volatile("ldmatrix.sync.aligned.m8n8.x4.shared.b16 {%0,%1,%2,%3}, [%4];"
        : "=r"(r[0]), "=r"(r[1]), "=r"(r[2]), "=r"(r[3]) : "r"(addr));
}
__device__ __forceinline__ void mma16816h(float* c, const uint32_t* a, uint32_t b0, uint32_t b1) {
    asm volatile("mma.sync.aligned.m16n8k16.row.col.f32.f16.f16.f32 "
        "{%0,%1,%2,%3}, {%4,%5,%6,%7}, {%8,%9}, {%0,%1,%2,%3};"
        : "+f"(c[0]), "+f"(c[1]), "+f"(c[2]), "+f"(c[3])
        : "r"(a[0]), "r"(a[1]), "r"(a[2]), "r"(a[3]), "r"(b0), "r"(b1));
}

// ---------------- K1: input LayerNorm (over C), output n-major (NT, C) ----
__global__ void ln_in_kernel(const float* __restrict__ x,
                             const float* __restrict__ w,
                             const float* __restrict__ bias) {
    int b  = blockIdx.y;
    int tid = threadIdx.x;
    int lx = tid & 31;
    int ty = tid >> 5;
    int l0 = blockIdx.x * 32;
    __shared__ float T[CDIM][33];
    __shared__ float sS[8][32], sQ[8][32], sMean[32], sR[32];

    const float* xb = x + (size_t)b * CDIM * LSEQ + l0 + lx;
    float s = 0.f, q = 0.f;
    for (int c = ty; c < CDIM; c += 8) {
        float v = xb[(size_t)c * LSEQ];
        T[c][lx] = v;
        s += v; q += v * v;
    }
    sS[ty][lx] = s; sQ[ty][lx] = q;
    __syncthreads();
    if (ty == 0) {
        float ts = 0.f, tq = 0.f;
        #pragma unroll
        for (int i = 0; i < 8; i++) { ts += sS[i][lx]; tq += sQ[i][lx]; }
        float m   = ts * (1.f / CDIM);
        float var = tq * (1.f / CDIM) - m * m;
        sMean[lx] = m;
        sR[lx]    = rsqrtf(var + 1e-5f);
    }
    __syncthreads();
    int c = tid;
    float wc = w[c], bc = bias[c];
    #pragma unroll 4
    for (int l = 0; l < 32; l++) {
        float v = T[c][l];
        g_u[(size_t)(b * LSEQ + l0 + l) * CDIM + c] = (v - sMean[l]) * sR[l] * wc + bc;
    }
}

// ---------------- K2: tensor-core TN GEMM, pure fp16 single-term ------------
// C[M,N] = A[M,K] * Bn[N,K]^T.  BM=128 BN=64 BK=32; 8 warps 4(m)x2(n).
// A, B both rounded to fp16. err ~2-3e-4 rel (RSS of two 2^-11 roundings).
__global__ __launch_bounds__(256, 2)
void gemm_tc_kernel(const float* __restrict__ A, const float* __restrict__ Bn,
                    float* __restrict__ C, int M, int N, int K) {
    __shared__ __half Ah[128][40], Bh[64][40];
    const int tid = threadIdx.x, lane = tid & 31, wid = tid >> 5;
    const int m0 = blockIdx.y * 128, n0 = blockIdx.x * 64;
    const int wm = (wid & 3) * 32;
    const int wn = (wid >> 2) * 32;
    const int lr = lane & 15;
    const int lc = (lane & 16) ? 8 : 0;

    float acc[2][4][4];
    #pragma unroll
    for (int mi = 0; mi < 2; mi++)
        #pragma unroll
        for (int nf = 0; nf < 4; nf++)
            #pragma unroll
            for (int e = 0; e < 4; e++) acc[mi][nf][e] = 0.f;

    const int grow = tid >> 3;           // 0..31
    const int gcol = (tid & 7) << 2;     // 0..28

    const float* Abase = A + (size_t)(m0 + grow) * K + gcol;
    const float* Bbase = Bn + (size_t)(n0 + grow) * K + gcol;

    float4 va[4], vb[2];
    #pragma unroll
    for (int i = 0; i < 4; i++) va[i] = *(const float4*)(Abase + (size_t)(32 * i) * K);
    #pragma unroll
    for (int i = 0; i < 2; i++) vb[i] = *(const float4*)(Bbase + (size_t)(32 * i) * K);

    const int nk = K >> 5;
    for (int kt = 0; kt < nk; kt++) {
        // ---- store+convert current regs to smem ----
        #pragma unroll
        for (int i = 0; i < 4; i++) {
            int r = grow + 32 * i;
            float4 v = va[i];
            __half2 hh0, hh1;
            hh0.x = __float2half(v.x); hh0.y = __float2half(v.y);
            hh1.x = __float2half(v.z); hh1.y = __float2half(v.w);
            *(__half2*)&Ah[r][gcol]     = hh0;
            *(__half2*)&Ah[r][gcol + 2] = hh1;
        }
        #pragma unroll
        for (int i = 0; i < 2; i++) {
            int r = grow + 32 * i;
            float4 v = vb[i];
            __half2 hh0, hh1;
            hh0.x = __float2half(v.x); hh0.y = __float2half(v.y);
            hh1.x = __float2half(v.z); hh1.y = __float2half(v.w);
            *(__half2*)&Bh[r][gcol]     = hh0;
            *(__half2*)&Bh[r][gcol + 2] = hh1;
        }
        __syncthreads();

        // ---- prefetch next k-tile into regs (overlaps MMA section) ----
        if (kt + 1 < nk) {
            const float* Ap = Abase + (kt + 1) * 32;
            const float* Bp = Bbase + (kt + 1) * 32;
            #pragma unroll
            for (int i = 0; i < 4; i++) va[i] = *(const float4*)(Ap + (size_t)(32 * i) * K);
            #pragma unroll
            for (int i = 0; i < 2; i++) vb[i] = *(const float4*)(Bp + (size_t)(32 * i) * K);
        }

        #pragma unroll
        for (int kk = 0; kk < 2; kk++) {
            const int k16 = kk * 16;
            uint32_t ah[2][4], bh[2][4];
            #pragma unroll
            for (int mi = 0; mi < 2; mi++)
                ldsm4(ah[mi], s2u(&Ah[wm + mi * 16 + lr][k16 + lc]));
            #pragma unroll
            for (int nj = 0; nj < 2; nj++)
                ldsm4(bh[nj], s2u(&Bh[wn + nj * 16 + lr][k16 + lc]));
            #pragma unroll
            for (int mi = 0; mi < 2; mi++)
                #pragma unroll
                for (int nf = 0; nf < 4; nf++) {
                    int nj = nf >> 1, sub = nf & 1;
                    mma16816h(acc[mi][nf], ah[mi], bh[nj][sub], bh[nj][sub + 2]);
                }
        }
        __syncthreads();
    }

    #pragma unroll
    for (int mi = 0; mi < 2; mi++)
        #pragma unroll
        for (int nf = 0; nf < 4; nf++) {
            int row = m0 + wm + mi * 16 + (lane >> 2);
            int col = n0 + wn + nf * 8 + ((lane & 3) << 1);
            float2 v0; v0.x = acc[mi][nf][0]; v0.y = acc[mi][nf][1];
            float2 v1; v1.x = acc[mi][nf][2]; v1.y = acc[mi][nf][3];
            *(float2*)&C[(size_t)row * N + col]       = v0;
            *(float2*)&C[(size_t)(row + 8) * N + col] = v1;
        }
}

// ---------------- K3: x_proj split-K partials + fused conv+SiLU -------------
// grid (NT/64, 4). Block computes conv+silu for its 128-d x 64-n tile,
// writes g_xc once, and accumulates the 48x64 x_proj partial.
__global__ void xproj_part_kernel(const float* __restrict__ W,
                                  const float* __restrict__ cw,
                                  const float* __restrict__ cb) {
    __shared__ float Ws[48][64];
    __shared__ float Xr[64][68];     // raw xz, col j <-> n0-4+j
    __shared__ float Xs[64][68];     // conv+silu, col c <-> n0+c
    __shared__ float Cw[64][4];
    __shared__ float Cb[64];
    int t  = threadIdx.x;
    int n0 = blockIdx.x * 64;
    int ks = blockIdx.y;
    int tn = t & 63, tk = t >> 6;
    bool seqstart = (n0 & (LSEQ - 1)) == 0;
    float acc[12];
    #pragma unroll
    for (int j = 0; j < 12; j++) acc[j] = 0.f;

    for (int cc = 0; cc < 2; cc++) {
        int d0 = ks * 128 + cc * 64;
        __syncthreads();
        for (int i = t; i < 768; i += 256) {
            int r = i >> 4, c4 = (i & 15) << 2;
            *(float4*)&Ws[r][c4] = *(const float4*)&W[(size_t)r * DIN + d0 + c4];
        }
        if (t < 64) {
            *(float4*)&Cw[t][0] = *(const float4*)&cw[(d0 + t) * 4];
            Cb[t] = cb[d0 + t];
        }
        for (int i = t; i < 1024; i += 256) {      // main cols j=4..67
            int r = i >> 4, c4 = (i & 15) << 2;
            *(float4*)&Xr[r][4 + c4] = *(const float4*)&g_xz[(size_t)(d0 + r) * NT + n0 + c4];
        }
        if (t < 192) {                              // history cols j=1..3
            int r = t / 3, j = t - r * 3;
            Xr[r][1 + j] = seqstart ? 0.f : g_xz[(size_t)(d0 + r) * NT + n0 - 3 + j];
        }
        __syncthreads();
        for (int i = t; i < 4096; i += 256) {
            int r = i >> 6, c = i & 63;
            float v = Cb[r];
            v = fmaf(Cw[r][3], Xr[r][c + 4], v);
            v = fmaf(Cw[r][2], Xr[r][c + 3], v);
            v = fmaf(Cw[r][1], Xr[r][c + 2], v);
            v = fmaf(Cw[r][0], Xr[r][c + 1], v);
            float xc = v / (1.f + __expf(-v));
            Xs[r][c] = xc;
            g_xc[(size_t)(d0 + r) * NT + n0 + c] = xc;
        }
        __syncthreads();
        #pragma unroll 4
        for (int dd = 0; dd < 64; dd++) {
            float xv = Xs[dd][tn];
            #pragma unroll
            for (int j = 0; j < 12; j++)
                acc[j] = fmaf(xv, Ws[tk * 12 + j][dd], acc[j]);
        }
    }
    int n = n0 + tn;
    #pragma unroll
    for (int j = 0; j < 12; j++) {
        int k = tk * 12 + j;
        g_xpart[((size_t)ks * 48 + k) * NT + n] = acc[j];
    }
}

// ---------------- K4: reduce partials -> dt/Bm/Cm in (n,16) layout ----------
__global__ void xred_kernel() {
    int idx = blockIdx.x * 256 + threadIdx.x;       // 48 * NT
    int k = idx / NT, n = idx - k * NT;
    float s = g_xpart[(size_t)k * NT + n]
            + g_xpart[((size_t)48 + k) * NT + n]
            + g_xpart[((size_t)96 + k) * NT + n]
            + g_xpart[((size_t)144 + k) * NT + n];
    if (k < DTRANK)                g_dt[(size_t)n * 16 + k] = s;
    else if (k < DTRANK + DSTATE)  g_Bm[(size_t)n * 16 + (k - DTRANK)] = s;
    else                           g_Cm[(size_t)n * 16 + (k - DTRANK - DSTATE)] = s;
}

// ---------------- K5: delta = softplus(dt @ dtw^T + dtb), smem-tiled --------
__global__ void delta_kernel(const float* __restrict__ dtw,
                             const float* __restrict__ dtb) {
    __shared__ float sDt[256][17];
    __shared__ float sW[128][17];
    __shared__ float sB[128];
    int t = threadIdx.x;
    int n0 = blockIdx.x * 256;
    int dseg = blockIdx.y * 128;

    for (int i = t; i < 256 * 4; i += 256) {
        int r = i >> 2, c4 = (i & 3) << 2;
        float4 v = *(const float4*)&g_dt[(size_t)(n0 + r) * 16 + c4];
        sDt[r][c4 + 0] = v.x; sDt[r][c4 + 1] = v.y;
        sDt[r][c4 + 2] = v.z; sDt[r][c4 + 3] = v.w;
    }
    for (int i = t; i < 128 * 4; i += 256) {
        int r = i >> 2, c4 = (i & 3) << 2;
        float4 v = *(const float4*)&dtw[(size_t)(dseg + r) * 16 + c4];
        sW[r][c4 + 0] = v.x; sW[r][c4 + 1] = v.y;
        sW[r][c4 + 2] = v.z; sW[r][c4 + 3] = v.w;
    }
    if (t < 128) sB[t] = dtb[dseg + t];
    __syncthreads();

    int n = n0 + t;
    for (int dd = 0; dd < 128; dd++) {
        float s = sB[dd];
        #pragma unroll
        for (int k = 0; k < 16; k++)
            s = fmaf(sDt[t][k], sW[dd][k], s);
        float delta = (s > 20.f) ? s : log1pf(__expf(s));
        g_delta[(size_t)(dseg + dd) * NT + n] = delta;
    }
}

// ---------------- K6a: chunk scan pass1 — smem-shared B chunk ---------------
__global__ void scan_p1_kernel(const float* __restrict__ Alog) {
    __shared__ float sB[CHLEN][16];
    int b  = blockIdx.z;
    int ch = blockIdx.y;
    int g  = threadIdx.x >> 4;
    int nl = threadIdx.x & 15;
    int d0 = blockIdx.x * 128;
    int base = b * LSEQ + ch * CHLEN;

    {
        int t = threadIdx.x;
        float4 v = *(const float4*)&g_Bm[((size_t)base) * 16 + t * 4];
        *(float4*)&sB[(t * 4) >> 4][(t * 4) & 15] = v;
    }
    __syncthreads();

    for (int dt = 0; dt < 8; dt++) {
        int d = d0 + dt * 16 + g;
        float Adn = -__expf(Alog[d * DSTATE + nl]);
        float P = 1.f, q = 0.f;
        const float* drow  = g_delta + (size_t)d * NT + base;
        const float* xcrow = g_xc    + (size_t)d * NT + base;
        #pragma unroll 4
        for (int l = 0; l < CHLEN; l++) {
            float delta = drow[l];
            float dA = __expf(delta * Adn);
            q = fmaf(dA, q, delta * sB[l][nl] * xcrow[l]);
            P *= dA;
        }
        size_t idx = ((size_t)(b * NCHUNK + ch) * DIN + d) * 16 + nl;
        g_P[idx] = P;
        g_q[idx] = q;
    }
}

// ---------------- K6b: prefix over chunks -> h0 -----------------------------
__global__ void scan_p2_kernel() {
    int idx = blockIdx.x * 256 + threadIdx.x;
    int n = idx & 15;
    int d = (idx >> 4) & (DIN - 1);
    int b = idx >> 13;
    float h = 0.f;
    #pragma unroll
    for (int ch = 0; ch < NCHUNK; ch++) {
        size_t p = ((size_t)(b * NCHUNK + ch) * DIN + d) * 16 + n;
        g_h0[p] = h;
        h = fmaf(g_P[p], h, g_q[p]);
    }
}

// ---------------- K6c: replay + y + gating — smem-shared B/C chunks ---------
__global__ void scan_p3_kernel(const float* __restrict__ Alog,
                               const float* __restrict__ Dp) {
    __shared__ float sB[CHLEN][16];
    __shared__ float sC[CHLEN][16];
    int b  = blockIdx.z;
    int ch = blockIdx.y;
    int g  = threadIdx.x >> 4;
    int nl = threadIdx.x & 15;
    int d0 = blockIdx.x * 128;
    int base = b * LSEQ + ch * CHLEN;

    {
        int t = threadIdx.x;
        float4 v = *(const float4*)&g_Bm[((size_t)base) * 16 + t * 4];
        *(float4*)&sB[(t * 4) >> 4][(t * 4) & 15] = v;
        float4 w = *(const float4*)&g_Cm[((size_t)base) * 16 + t * 4];
        *(float4*)&sC[(t * 4) >> 4][(t * 4) & 15] = w;
    }
    __syncthreads();

    for (int dt = 0; dt < 8; dt++) {
        int d = d0 + dt * 16 + g;
        float Adn = -__expf(Alog[d * DSTATE + nl]);
        float Dd  = Dp[d];
        float h = g_h0[((size_t)(b * NCHUNK + ch) * DIN + d) * 16 + nl];
        const float* drow  = g_delta + (size_t)d * NT + base;
        const float* xcrow = g_xc    + (size_t)d * NT + base;
        const float* zrow  = g_xz + (size_t)(DIN + d) * NT + base;
        #pragma unroll 4
        for (int l = 0; l < CHLEN; l++) {
            float delta = drow[l];
            float xcv = xcrow[l];
            float dA = __expf(delta * Adn);
            h = fmaf(dA, h, delta * sB[l][nl] * xcv);
            float yv = h * sC[l][nl];
            yv += __shfl_xor_sync(0xffffffffu, yv, 1);
            yv += __shfl_xor_sync(0xffffffffu, yv, 2);
            yv += __shfl_xor_sync(0xffffffffu, yv, 4);
            yv += __shfl_xor_sync(0xffffffffu, yv, 8);
            if (nl == 0) {
                float zl = zrow[l];
                float silu = zl / (1.f + __expf(-zl));
                g_y[(size_t)(base + l) * DIN + d] = (yv + Dd * xcv) * silu;
            }
        }
    }
}

// ---------------- K7: residual + output LayerNorm, write (B,C,L,1) ----------
__global__ void ln_out_kernel(const float* __restrict__ x,
                              const float* __restrict__ w,
                              const float* __restrict__ bias,
                              float* __restrict__ out) {
    int b  = blockIdx.y;
    int lx = threadIdx.x;
    int ty = threadIdx.y;
    int l  = blockIdx.x * 32 + lx;
    __shared__ float sS[8][32], sQ[8][32], sMean[32], sR[32];

    const float* xb = x + (size_t)b * CDIM * LSEQ + l;
    const float* ob = g_op + (size_t)b * LSEQ + l;
    float s = 0.f, q = 0.f;
    for (int c = ty; c < CDIM; c += 8) {
        float v = ob[(size_t)c * NT] + xb[(size_t)c * LSEQ];
        s += v; q += v * v;
    }
    sS[ty][lx] = s; sQ[ty][lx] = q;
    __syncthreads();
    if (ty == 0) {
        float ts = 0.f, tq = 0.f;
        #pragma unroll
        for (int i = 0; i < 8; i++) { ts += sS[i][lx]; tq += sQ[i][lx]; }
        float m   = ts * (1.f / CDIM);
        float var = tq * (1.f / CDIM) - m * m;
        sMean[lx] = m;
        sR[lx]    = rsqrtf(var + 1e-5f);
    }
    __syncthreads();
    float m = sMean[lx], r = sR[lx];
    float* outb = out + (size_t)b * CDIM * LSEQ + l;
    for (int c = ty; c < CDIM; c += 8) {
        float v = ob[(size_t)c * NT] + xb[(size_t)c * LSEQ];
        outb[(size_t)c * LSEQ] = (v - m) * r * w[c] + bias[c];
    }
}

// ---------------- launch -----------------------------------------------------
extern "C" void kernel_launch(void* const* d_in, const int* in_sizes, int n_in,
                              void* d_out, int out_size) {
    const float* x         = (const float*)d_in[0];
    const float* ln_w      = (const float*)d_in[1];
    const float* ln_b      = (const float*)d_in[2];
    const float* in_proj_w = (const float*)d_in[3];
    const float* conv_w    = (const float*)d_in[4];
    const float* conv_b    = (const float*)d_in[5];
    const float* x_proj_w  = (const float*)d_in[6];
    const float* dt_proj_w = (const float*)d_in[7];
    const float* dt_proj_b = (const float*)d_in[8];
    const float* A_log     = (const float*)d_in[9];
    const float* Dv        = (const float*)d_in[10];
    const float* out_proj_w= (const float*)d_in[11];
    float* out = (float*)d_out;

    float *p_u, *p_xz, *p_y, *p_op;
    cudaGetSymbolAddress((void**)&p_u,  g_u);
    cudaGetSymbolAddress((void**)&p_xz, g_xz);
    cudaGetSymbolAddress((void**)&p_y,  g_y);
    cudaGetSymbolAddress((void**)&p_op, g_op);

    ln_in_kernel<<<dim3(LSEQ / 32, BATCH), 256>>>(x, ln_w, ln_b);

    // in_proj: (1024,256) @ (8192,256)^T
    gemm_tc_kernel<<<dim3(NT / 64, (2 * DIN) / 128), 256>>>(
        in_proj_w, p_u, p_xz, 2 * DIN, NT, CDIM);

    xproj_part_kernel<<<dim3(NT / 64, 4), 256>>>(x_proj_w, conv_w, conv_b);
    xred_kernel<<<(48 * NT) / 256, 256>>>();

    delta_kernel<<<dim3(NT / 256, 4), 256>>>(dt_proj_w, dt_proj_b);

    scan_p1_kernel<<<dim3(4, NCHUNK, BATCH), 256>>>(A_log);
    scan_p2_kernel<<<dim3(BATCH * DIN * 16 / 256), 256>>>();
    scan_p3_kernel<<<dim3(4, NCHUNK, BATCH), 256>>>(A_log, Dv);

    // out_proj: (256,512) @ (8192,512)^T
    gemm_tc_kernel<<<dim3(NT / 64, CDIM / 128), 256>>>(
        out_proj_w, p_y, p_op, CDIM, NT, DIN);

    ln_out_kernel<<<dim3(LSEQ / 32, BATCH), dim3(32, 8)>>>(x, ln_w, ln_b, out);
}

// round 14
// speedup vs baseline: 1.2356x; 1.0172x over previous
#include <cuda_runtime.h>
#include <cuda_fp16.h>
#include <math.h>
#include <stdint.h>

#define LSEQ   2048
#define BATCH  4
#define NT     8192          // BATCH * LSEQ
#define CDIM   256
#define DIN    512
#define DSTATE 16
#define DTRANK 16
#define NCHUNK 32
#define CHLEN  64            // LSEQ / NCHUNK

// ---------------- scratch (static __device__, no allocs) ----------------
__device__ __half g_u    [NT * CDIM];       // 4 MB (B*L, C) normalized input (fp16)
__device__ __half g_xz   [2 * DIN * NT];    // 16 MB (2*DIN, B*L) in_proj out (fp16)
__device__ __half g_xc   [DIN * NT];        //  8 MB (DIN, B*L) conv+silu (fp16)
__device__ float  g_xpart[4 * 48 * NT];     //  6 MB x_proj split-K partials
__device__ float  g_dt   [NT * DTRANK];     // (B*L, 16)
__device__ float  g_Bm   [NT * DSTATE];     // (B*L, 16)
__device__ float  g_Cm   [NT * DSTATE];     // (B*L, 16)
__device__ __half g_delta[DIN * NT];        //  8 MB (DIN, B*L) softplus (fp16)
__device__ __half g_y    [NT * DIN];        //  8 MB (B*L, DIN) gated y (fp16)
__device__ float  g_op   [CDIM * NT];       //  8 MB (C, B*L) out_proj out
__device__ float  g_P    [BATCH * NCHUNK * DIN * DSTATE];
__device__ float  g_q    [BATCH * NCHUNK * DIN * DSTATE];
__device__ float  g_h0   [BATCH * NCHUNK * DIN * DSTATE];

__device__ __forceinline__ uint32_t s2u(const void* p) {
    return (uint32_t)__cvta_generic_to_shared(p);
}
__device__ __forceinline__ void ldsm4(uint32_t* r, uint32_t addr) {
    asm volatile("ldmatrix.sync.aligned.m8n8.x4.shared.b16 {%0,%1,%2,%3}, [%4];"
        : "=r"(r[0]), "=r"(r[1]), "=r"(r[2]), "=r"(r[3]) : "r"(addr));
}
__device__ __forceinline__ void mma16816h(float* c, const uint32_t* a, uint32_t b0, uint32_t b1) {
    asm volatile("mma.sync.aligned.m16n8k16.row.col.f32.f16.f16.f32 "
        "{%0,%1,%2,%3}, {%4,%5,%6,%7}, {%8,%9}, {%0,%1,%2,%3};"
        : "+f"(c[0]), "+f"(c[1]), "+f"(c[2]), "+f"(c[3])
        : "r"(a[0]), "r"(a[1]), "r"(a[2]), "r"(a[3]), "r"(b0), "r"(b1));
}

// ---------------- K1: input LayerNorm (over C), emit fp16 (NT, C) -----------
__global__ void ln_in_kernel(const float* __restrict__ x,
                             const float* __restrict__ w,
                             const float* __restrict__ bias) {
    int b  = blockIdx.y;
    int tid = threadIdx.x;
    int lx = tid & 31;
    int ty = tid >> 5;
    int l0 = blockIdx.x * 32;
    __shared__ float T[CDIM][33];
    __shared__ float sS[8][32], sQ[8][32], sMean[32], sR[32];

    const float* xb = x + (size_t)b * CDIM * LSEQ + l0 + lx;
    float s = 0.f, q = 0.f;
    for (int c = ty; c < CDIM; c += 8) {
        float v = xb[(size_t)c * LSEQ];
        T[c][lx] = v;
        s += v; q += v * v;
    }
    sS[ty][lx] = s; sQ[ty][lx] = q;
    __syncthreads();
    if (ty == 0) {
        float ts = 0.f, tq = 0.f;
        #pragma unroll
        for (int i = 0; i < 8; i++) { ts += sS[i][lx]; tq += sQ[i][lx]; }
        float m   = ts * (1.f / CDIM);
        float var = tq * (1.f / CDIM) - m * m;
        sMean[lx] = m;
        sR[lx]    = rsqrtf(var + 1e-5f);
    }
    __syncthreads();
    int c = tid;
    float wc = w[c], bc = bias[c];
    #pragma unroll 4
    for (int l = 0; l < 32; l++) {
        float v = T[c][l];
        g_u[(size_t)(b * LSEQ + l0 + l) * CDIM + c] =
            __float2half((v - sMean[l]) * sR[l] * wc + bc);
    }
}

// ---------------- K2: TN GEMM, fp32 A (cvt in-kernel) x fp16 B --------------
// C[M,N] = A[M,K] * Bh[N,K]^T.  BM=128 BN=64 BK=32; 8 warps 4(m)x2(n).
// OutT = __half (in_proj -> g_xz) or float (out_proj -> g_op).
template <typename OutT>
__global__ __launch_bounds__(256, 2)
void gemm_h_kernel(const float* __restrict__ A, const __half* __restrict__ Bg,
                   OutT* __restrict__ C, int M, int N, int K) {
    __shared__ __half Ah[128][40], Bh[64][40];
    const int tid = threadIdx.x, lane = tid & 31, wid = tid >> 5;
    const int m0 = blockIdx.y * 128, n0 = blockIdx.x * 64;
    const int wm = (wid & 3) * 32;
    const int wn = (wid >> 2) * 32;
    const int lr = lane & 15;
    const int lc = (lane & 16) ? 8 : 0;

    float acc[2][4][4];
    #pragma unroll
    for (int mi = 0; mi < 2; mi++)
        #pragma unroll
        for (int nf = 0; nf < 4; nf++)
            #pragma unroll
            for (int e = 0; e < 4; e++) acc[mi][nf][e] = 0.f;

    const int grow = tid >> 3;           // 0..31  (A loader)
    const int gcol = (tid & 7) << 2;     // 0..28
    const int br = tid >> 2;             // 0..63  (B loader)
    const int bc8 = (tid & 3) << 3;      // 0,8,16,24 halves

    const float*  Abase = A  + (size_t)(m0 + grow) * K + gcol;
    const __half* Bbase = Bg + (size_t)(n0 + br) * K + bc8;

    float4 va[4];
    uint4  vb;
    #pragma unroll
    for (int i = 0; i < 4; i++) va[i] = *(const float4*)(Abase + (size_t)(32 * i) * K);
    vb = *(const uint4*)(Bbase);

    const int nk = K >> 5;
    for (int kt = 0; kt < nk; kt++) {
        // ---- store current regs to smem (A converts, B raw) ----
        #pragma unroll
        for (int i = 0; i < 4; i++) {
            int r = grow + 32 * i;
            float4 v = va[i];
            __half2 hh0, hh1;
            hh0.x = __float2half(v.x); hh0.y = __float2half(v.y);
            hh1.x = __float2half(v.z); hh1.y = __float2half(v.w);
            *(__half2*)&Ah[r][gcol]     = hh0;
            *(__half2*)&Ah[r][gcol + 2] = hh1;
        }
        *(uint4*)&Bh[br][bc8] = vb;
        __syncthreads();

        // ---- prefetch next k-tile into regs ----
        if (kt + 1 < nk) {
            const float*  Ap = Abase + (kt + 1) * 32;
            const __half* Bp = Bbase + (kt + 1) * 32;
            #pragma unroll
            for (int i = 0; i < 4; i++) va[i] = *(const float4*)(Ap + (size_t)(32 * i) * K);
            vb = *(const uint4*)(Bp);
        }

        #pragma unroll
        for (int kk = 0; kk < 2; kk++) {
            const int k16 = kk * 16;
            uint32_t ah[2][4], bh[2][4];
            #pragma unroll
            for (int mi = 0; mi < 2; mi++)
                ldsm4(ah[mi], s2u(&Ah[wm + mi * 16 + lr][k16 + lc]));
            #pragma unroll
            for (int nj = 0; nj < 2; nj++)
                ldsm4(bh[nj], s2u(&Bh[wn + nj * 16 + lr][k16 + lc]));
            #pragma unroll
            for (int mi = 0; mi < 2; mi++)
                #pragma unroll
                for (int nf = 0; nf < 4; nf++) {
                    int nj = nf >> 1, sub = nf & 1;
                    mma16816h(acc[mi][nf], ah[mi], bh[nj][sub], bh[nj][sub + 2]);
                }
        }
        __syncthreads();
    }

    #pragma unroll
    for (int mi = 0; mi < 2; mi++)
        #pragma unroll
        for (int nf = 0; nf < 4; nf++) {
            int row = m0 + wm + mi * 16 + (lane >> 2);
            int col = n0 + wn + nf * 8 + ((lane & 3) << 1);
            if constexpr (sizeof(OutT) == 2) {
                __half2 h0, h1;
                h0.x = __float2half(acc[mi][nf][0]); h0.y = __float2half(acc[mi][nf][1]);
                h1.x = __float2half(acc[mi][nf][2]); h1.y = __float2half(acc[mi][nf][3]);
                *(__half2*)&C[(size_t)row * N + col]       = h0;
                *(__half2*)&C[(size_t)(row + 8) * N + col] = h1;
            } else {
                float2 v0; v0.x = acc[mi][nf][0]; v0.y = acc[mi][nf][1];
                float2 v1; v1.x = acc[mi][nf][2]; v1.y = acc[mi][nf][3];
                *(float2*)&C[(size_t)row * N + col]       = v0;
                *(float2*)&C[(size_t)(row + 8) * N + col] = v1;
            }
        }
}

// ---------------- K3: x_proj split-K partials + fused conv+SiLU -------------
// grid (NT/64, 4). Block computes conv+silu for its 128-d x 64-n tile,
// writes g_xc (fp16) once, and accumulates the 48x64 x_proj partial.
__global__ void xproj_part_kernel(const float* __restrict__ W,
                                  const float* __restrict__ cw,
                                  const float* __restrict__ cb) {
    __shared__ float Ws[48][64];
    __shared__ float Xr[64][68];     // raw xz, col j <-> n0-4+j
    __shared__ float Xs[64][68];     // conv+silu, col c <-> n0+c
    __shared__ float Cw[64][4];
    __shared__ float Cb[64];
    int t  = threadIdx.x;
    int n0 = blockIdx.x * 64;
    int ks = blockIdx.y;
    int tn = t & 63, tk = t >> 6;
    bool seqstart = (n0 & (LSEQ - 1)) == 0;
    float acc[12];
    #pragma unroll
    for (int j = 0; j < 12; j++) acc[j] = 0.f;

    for (int cc = 0; cc < 2; cc++) {
        int d0 = ks * 128 + cc * 64;
        __syncthreads();
        for (int i = t; i < 768; i += 256) {
            int r = i >> 4, c4 = (i & 15) << 2;
            *(float4*)&Ws[r][c4] = *(const float4*)&W[(size_t)r * DIN + d0 + c4];
        }
        if (t < 64) {
            *(float4*)&Cw[t][0] = *(const float4*)&cw[(d0 + t) * 4];
            Cb[t] = cb[d0 + t];
        }
        // main cols j=4..67: 64 rows x 64 halves, 8 halves per 16B load
        for (int i = t; i < 512; i += 256) {
            int r = i >> 3, c8 = (i & 7) << 3;
            uint4 raw = *(const uint4*)&g_xz[(size_t)(d0 + r) * NT + n0 + c8];
            const __half2* hp = (const __half2*)&raw;
            #pragma unroll
            for (int j = 0; j < 4; j++) {
                float2 f = __half22float2(hp[j]);
                Xr[r][4 + c8 + j * 2]     = f.x;
                Xr[r][4 + c8 + j * 2 + 1] = f.y;
            }
        }
        if (t < 192) {                              // history cols j=1..3
            int r = t / 3, j = t - r * 3;
            Xr[r][1 + j] = seqstart ? 0.f
                : __half2float(g_xz[(size_t)(d0 + r) * NT + n0 - 3 + j]);
        }
        __syncthreads();
        for (int i = t; i < 4096; i += 256) {
            int r = i >> 6, c = i & 63;
            float v = Cb[r];
            v = fmaf(Cw[r][3], Xr[r][c + 4], v);
            v = fmaf(Cw[r][2], Xr[r][c + 3], v);
            v = fmaf(Cw[r][1], Xr[r][c + 2], v);
            v = fmaf(Cw[r][0], Xr[r][c + 1], v);
            float xc = v / (1.f + __expf(-v));
            Xs[r][c] = xc;
            g_xc[(size_t)(d0 + r) * NT + n0 + c] = __float2half(xc);
        }
        __syncthreads();
        #pragma unroll 4
        for (int dd = 0; dd < 64; dd++) {
            float xv = Xs[dd][tn];
            #pragma unroll
            for (int j = 0; j < 12; j++)
                acc[j] = fmaf(xv, Ws[tk * 12 + j][dd], acc[j]);
        }
    }
    int n = n0 + tn;
    #pragma unroll
    for (int j = 0; j < 12; j++) {
        int k = tk * 12 + j;
        g_xpart[((size_t)ks * 48 + k) * NT + n] = acc[j];
    }
}

// ---------------- K4: reduce partials -> dt/Bm/Cm in (n,16) layout ----------
__global__ void xred_kernel() {
    int idx = blockIdx.x * 256 + threadIdx.x;       // 48 * NT
    int k = idx / NT, n = idx - k * NT;
    float s = g_xpart[(size_t)k * NT + n]
            + g_xpart[((size_t)48 + k) * NT + n]
            + g_xpart[((size_t)96 + k) * NT + n]
            + g_xpart[((size_t)144 + k) * NT + n];
    if (k < DTRANK)                g_dt[(size_t)n * 16 + k] = s;
    else if (k < DTRANK + DSTATE)  g_Bm[(size_t)n * 16 + (k - DTRANK)] = s;
    else                           g_Cm[(size_t)n * 16 + (k - DTRANK - DSTATE)] = s;
}

// ---------------- K5: delta = softplus(dt @ dtw^T + dtb), smem-tiled --------
__global__ void delta_kernel(const float* __restrict__ dtw,
                             const float* __restrict__ dtb) {
    __shared__ float sDt[256][17];
    __shared__ float sW[128][17];
    __shared__ float sB[128];
    int t = threadIdx.x;
    int n0 = blockIdx.x * 256;
    int dseg = blockIdx.y * 128;

    for (int i = t; i < 256 * 4; i += 256) {
        int r = i >> 2, c4 = (i & 3) << 2;
        float4 v = *(const float4*)&g_dt[(size_t)(n0 + r) * 16 + c4];
        sDt[r][c4 + 0] = v.x; sDt[r][c4 + 1] = v.y;
        sDt[r][c4 + 2] = v.z; sDt[r][c4 + 3] = v.w;
    }
    for (int i = t; i < 128 * 4; i += 256) {
        int r = i >> 2, c4 = (i & 3) << 2;
        float4 v = *(const float4*)&dtw[(size_t)(dseg + r) * 16 + c4];
        sW[r][c4 + 0] = v.x; sW[r][c4 + 1] = v.y;
        sW[r][c4 + 2] = v.z; sW[r][c4 + 3] = v.w;
    }
    if (t < 128) sB[t] = dtb[dseg + t];
    __syncthreads();

    int n = n0 + t;
    for (int dd = 0; dd < 128; dd++) {
        float s = sB[dd];
        #pragma unroll
        for (int k = 0; k < 16; k++)
            s = fmaf(sDt[t][k], sW[dd][k], s);
        float delta = (s > 20.f) ? s : log1pf(__expf(s));
        g_delta[(size_t)(dseg + dd) * NT + n] = __float2half(delta);
    }
}

// ---------------- K6a: chunk scan pass1 — smem-shared B chunk ---------------
__global__ void scan_p1_kernel(const float* __restrict__ Alog) {
    __shared__ float sB[CHLEN][16];
    int b  = blockIdx.z;
    int ch = blockIdx.y;
    int g  = threadIdx.x >> 4;
    int nl = threadIdx.x & 15;
    int d0 = blockIdx.x * 128;
    int base = b * LSEQ + ch * CHLEN;

    {
        int t = threadIdx.x;
        float4 v = *(const float4*)&g_Bm[((size_t)base) * 16 + t * 4];
        *(float4*)&sB[(t * 4) >> 4][(t * 4) & 15] = v;
    }
    __syncthreads();

    for (int dt = 0; dt < 8; dt++) {
        int d = d0 + dt * 16 + g;
        float Adn = -__expf(Alog[d * DSTATE + nl]);
        float P = 1.f, q = 0.f;
        const __half* drow  = g_delta + (size_t)d * NT + base;
        const __half* xcrow = g_xc    + (size_t)d * NT + base;
        #pragma unroll 4
        for (int l = 0; l < CHLEN; l++) {
            float delta = __half2float(drow[l]);
            float dA = __expf(delta * Adn);
            q = fmaf(dA, q, delta * sB[l][nl] * __half2float(xcrow[l]));
            P *= dA;
        }
        size_t idx = ((size_t)(b * NCHUNK + ch) * DIN + d) * 16 + nl;
        g_P[idx] = P;
        g_q[idx] = q;
    }
}

// ---------------- K6b: prefix over chunks -> h0 -----------------------------
__global__ void scan_p2_kernel() {
    int idx = blockIdx.x * 256 + threadIdx.x;
    int n = idx & 15;
    int d = (idx >> 4) & (DIN - 1);
    int b = idx >> 13;
    float h = 0.f;
    #pragma unroll
    for (int ch = 0; ch < NCHUNK; ch++) {
        size_t p = ((size_t)(b * NCHUNK + ch) * DIN + d) * 16 + n;
        g_h0[p] = h;
        h = fmaf(g_P[p], h, g_q[p]);
    }
}

// ---------------- K6c: replay + y + gating — emit y fp16 (NT, DIN) ----------
__global__ void scan_p3_kernel(const float* __restrict__ Alog,
                               const float* __restrict__ Dp) {
    __shared__ float sB[CHLEN][16];
    __shared__ float sC[CHLEN][16];
    int b  = blockIdx.z;
    int ch = blockIdx.y;
    int g  = threadIdx.x >> 4;
    int nl = threadIdx.x & 15;
    int d0 = blockIdx.x * 128;
    int base = b * LSEQ + ch * CHLEN;

    {
        int t = threadIdx.x;
        float4 v = *(const float4*)&g_Bm[((size_t)base) * 16 + t * 4];
        *(float4*)&sB[(t * 4) >> 4][(t * 4) & 15] = v;
        float4 w = *(const float4*)&g_Cm[((size_t)base) * 16 + t * 4];
        *(float4*)&sC[(t * 4) >> 4][(t * 4) & 15] = w;
    }
    __syncthreads();

    for (int dt = 0; dt < 8; dt++) {
        int d = d0 + dt * 16 + g;
        float Adn = -__expf(Alog[d * DSTATE + nl]);
        float Dd  = Dp[d];
        float h = g_h0[((size_t)(b * NCHUNK + ch) * DIN + d) * 16 + nl];
        const __half* drow  = g_delta + (size_t)d * NT + base;
        const __half* xcrow = g_xc    + (size_t)d * NT + base;
        const __half* zrow  = g_xz + (size_t)(DIN + d) * NT + base;
        #pragma unroll 4
        for (int l = 0; l < CHLEN; l++) {
            float delta = __half2float(drow[l]);
            float xcv = __half2float(xcrow[l]);
            float dA = __expf(delta * Adn);
            h = fmaf(dA, h, delta * sB[l][nl] * xcv);
            float yv = h * sC[l][nl];
            yv += __shfl_xor_sync(0xffffffffu, yv, 1);
            yv += __shfl_xor_sync(0xffffffffu, yv, 2);
            yv += __shfl_xor_sync(0xffffffffu, yv, 4);
            yv += __shfl_xor_sync(0xffffffffu, yv, 8);
            if (nl == 0) {
                float zl = __half2float(zrow[l]);
                float silu = zl / (1.f + __expf(-zl));
                g_y[(size_t)(base + l) * DIN + d] =
                    __float2half((yv + Dd * xcv) * silu);
            }
        }
    }
}

// ---------------- K7: residual + output LayerNorm, write (B,C,L,1) ----------
__global__ void ln_out_kernel(const float* __restrict__ x,
                              const float* __restrict__ w,
                              const float* __restrict__ bias,
                              float* __restrict__ out) {
    int b  = blockIdx.y;
    int lx = threadIdx.x;
    int ty = threadIdx.y;
    int l  = blockIdx.x * 32 + lx;
    __shared__ float sS[8][32], sQ[8][32], sMean[32], sR[32];

    const float* xb = x + (size_t)b * CDIM * LSEQ + l;
    const float* ob = g_op + (size_t)b * LSEQ + l;
    float s = 0.f, q = 0.f;
    for (int c = ty; c < CDIM; c += 8) {
        float v = ob[(size_t)c * NT] + xb[(size_t)c * LSEQ];
        s += v; q += v * v;
    }
    sS[ty][lx] = s; sQ[ty][lx] = q;
    __syncthreads();
    if (ty == 0) {
        float ts = 0.f, tq = 0.f;
        #pragma unroll
        for (int i = 0; i < 8; i++) { ts += sS[i][lx]; tq += sQ[i][lx]; }
        float m   = ts * (1.f / CDIM);
        float var = tq * (1.f / CDIM) - m * m;
        sMean[lx] = m;
        sR[lx]    = rsqrtf(var + 1e-5f);
    }
    __syncthreads();
    float m = sMean[lx], r = sR[lx];
    float* outb = out + (size_t)b * CDIM * LSEQ + l;
    for (int c = ty; c < CDIM; c += 8) {
        float v = ob[(size_t)c * NT] + xb[(size_t)c * LSEQ];
        outb[(size_t)c * LSEQ] = (v - m) * r * w[c] + bias[c];
    }
}

// ---------------- launch -----------------------------------------------------
extern "C" void kernel_launch(void* const* d_in, const int* in_sizes, int n_in,
                              void* d_out, int out_size) {
    const float* x         = (const float*)d_in[0];
    const float* ln_w      = (const float*)d_in[1];
    const float* ln_b      = (const float*)d_in[2];
    const float* in_proj_w = (const float*)d_in[3];
    const float* conv_w    = (const float*)d_in[4];
    const float* conv_b    = (const float*)d_in[5];
    const float* x_proj_w  = (const float*)d_in[6];
    const float* dt_proj_w = (const float*)d_in[7];
    const float* dt_proj_b = (const float*)d_in[8];
    const float* A_log     = (const float*)d_in[9];
    const float* Dv        = (const float*)d_in[10];
    const float* out_proj_w= (const float*)d_in[11];
    float* out = (float*)d_out;

    __half *p_u, *p_xz, *p_y;
    float  *p_op;
    cudaGetSymbolAddress((void**)&p_u,  g_u);
    cudaGetSymbolAddress((void**)&p_xz, g_xz);
    cudaGetSymbolAddress((void**)&p_y,  g_y);
    cudaGetSymbolAddress((void**)&p_op, g_op);

    ln_in_kernel<<<dim3(LSEQ / 32, BATCH), 256>>>(x, ln_w, ln_b);

    // in_proj: (1024,256) @ (8192,256)^T -> fp16 output
    gemm_h_kernel<__half><<<dim3(NT / 64, (2 * DIN) / 128), 256>>>(
        in_proj_w, p_u, p_xz, 2 * DIN, NT, CDIM);

    xproj_part_kernel<<<dim3(NT / 64, 4), 256>>>(x_proj_w, conv_w, conv_b);
    xred_kernel<<<(48 * NT) / 256, 256>>>();

    delta_kernel<<<dim3(NT / 256, 4), 256>>>(dt_proj_w, dt_proj_b);

    scan_p1_kernel<<<dim3(4, NCHUNK, BATCH), 256>>>(A_log);
    scan_p2_kernel<<<dim3(BATCH * DIN * 16 / 256), 256>>>();
    scan_p3_kernel<<<dim3(4, NCHUNK, BATCH), 256>>>(A_log, Dv);

    // out_proj: (256,512) @ (8192,512)^T -> fp32 output
    gemm_h_kernel<float><<<dim3(NT / 64, CDIM / 128), 256>>>(
        out_proj_w, p_y, p_op, CDIM, NT, DIN);

    ln_out_kernel<<<dim3(LSEQ / 32, BATCH), dim3(32, 8)>>>(x, ln_w, ln_b, out);
}